// round 7
// baseline (speedup 1.0000x reference)
#include <cuda_runtime.h>

// ZBL pair energy + segment-sum into per-atom energies.
//
// Inputs (metadata order; JAX default x64-off stores "int64" as int32):
//   d_in[0] Z               float32 [4]
//   d_in[1] r               float32 [E]          (E = 6,400,000)
//   d_in[2] per_atom_energy float32 [n_atoms,1]  (n_atoms = 100,000)
//   d_in[3] atom_types      int32   [n_atoms]
//   d_in[4] edge_index      int32   [2, E]
// Output: float32 [n_atoms, 1]

#define ZBL_QQ        7.1998225f        // 14.399645 * 0.5
#define ZBL_INV_A0    (1.0f / 0.4685f)
#define ZBL_INV_RMAX  (1.0f / 6.0f)
#define LOG2E         1.4426950408889634f

// Shared-memory LUT capacity: 6400 words * 16 types = 102400 atoms.
#define SMEM_WORDS 6400
// Fallback global packed buffer: 1M words = 16M atoms (4MB static).
#define MAX_PACK_WORDS (1 << 20)
__device__ unsigned g_packed_types[MAX_PACK_WORDS];

__device__ __forceinline__ float ex2_approx(float x) {
    float y; asm("ex2.approx.f32 %0, %1;" : "=f"(y) : "f"(x)); return y;
}
__device__ __forceinline__ float rcp_approx(float x) {
    float y; asm("rcp.approx.f32 %0, %1;" : "=f"(y) : "f"(x)); return y;
}

// Fused prep: out = per_atom_energy (float4 copy) AND pack types 2-bit/atom.
__global__ void prep_kernel(const float* __restrict__ pae,
                            float* __restrict__ out,
                            const int* __restrict__ types,
                            int n_atoms, int n_words)
{
    const int i = blockIdx.x * blockDim.x + threadIdx.x;
    const int nvec4 = n_atoms >> 2;

    if (i < nvec4)
        reinterpret_cast<float4*>(out)[i] =
            reinterpret_cast<const float4*>(pae)[i];
    if (i == 0)
        for (int a = nvec4 << 2; a < n_atoms; a++) out[a] = pae[a];

    if (i < n_words) {
        unsigned v = 0;
        const int base = i << 4;
        if (base + 16 <= n_atoms) {
            const int4* t4 = reinterpret_cast<const int4*>(types + base);
            #pragma unroll
            for (int q = 0; q < 4; q++) {
                int4 w = t4[q];
                v |= ((unsigned)w.x & 3u) << ((q * 4 + 0) * 2);
                v |= ((unsigned)w.y & 3u) << ((q * 4 + 1) * 2);
                v |= ((unsigned)w.z & 3u) << ((q * 4 + 2) * 2);
                v |= ((unsigned)w.w & 3u) << ((q * 4 + 3) * 2);
            }
        } else {
            for (int k = 0; k < 16; k++) {
                int a = base + k;
                unsigned t = (a < n_atoms) ? ((unsigned)types[a] & 3u) : 0u;
                v |= t << (k * 2);
            }
        }
        g_packed_types[i] = v;
    }
}

// Per-edge ZBL energy, scattered with atomicAdd. 8 edges per thread-iteration.
template <bool USE_SMEM>
__global__ void __launch_bounds__(256)
zbl_edge_kernel(const float* __restrict__ r,
                const int* __restrict__ e_i,   // edge_index row 0 (segment target)
                const int* __restrict__ e_j,   // edge_index row 1
                const float* __restrict__ Z,
                float* __restrict__ out,
                int E, int n_words)
{
    __shared__ unsigned s_pack[USE_SMEM ? SMEM_WORDS : 1];
    __shared__ float s_a1[16], s_a2[16], s_a3[16], s_a4[16], s_zzq[16];
    __shared__ float s_zp[4], s_z[4];

    const int tid = threadIdx.x;
    if (tid < 4) {
        float z = Z[tid];
        s_z[tid]  = z;
        s_zp[tid] = __powf(z, 0.23f);
    }
    __syncthreads();
    if (tid < 16) {
        int ti = tid >> 2, tj = tid & 3;
        float base = (s_zp[ti] + s_zp[tj]) * ZBL_INV_A0 * LOG2E;
        s_a1[tid] = -0.20162f * base;
        s_a2[tid] = -0.40290f * base;
        s_a3[tid] = -0.94229f * base;
        s_a4[tid] = -3.19980f * base;
        s_zzq[tid] = ZBL_QQ * s_z[ti] * s_z[tj];
    }
    if (USE_SMEM) {
        for (int w = tid; w < n_words; w += 256)
            s_pack[w] = g_packed_types[w];
    }
    __syncthreads();

    const unsigned* __restrict__ tbl = USE_SMEM ? s_pack : g_packed_types;

    const int nvec8  = E >> 3;          // 8 edges per iteration
    const int stride = gridDim.x * blockDim.x;

    for (int t = blockIdx.x * blockDim.x + tid; t < nvec8; t += stride) {
        // Front-batched wide loads: 6 x 16B (MLP = 6).
        const float4 rA = __ldg(reinterpret_cast<const float4*>(r) + 2 * t);
        const float4 rB = __ldg(reinterpret_cast<const float4*>(r) + 2 * t + 1);
        const int4   iA = __ldg(reinterpret_cast<const int4*>(e_i) + 2 * t);
        const int4   iB = __ldg(reinterpret_cast<const int4*>(e_i) + 2 * t + 1);
        const int4   jA = __ldg(reinterpret_cast<const int4*>(e_j) + 2 * t);
        const int4   jB = __ldg(reinterpret_cast<const int4*>(e_j) + 2 * t + 1);

        int   ii[8] = {iA.x, iA.y, iA.z, iA.w, iB.x, iB.y, iB.z, iB.w};
        int   jj[8] = {jA.x, jA.y, jA.z, jA.w, jB.x, jB.y, jB.z, jB.w};
        float rv[8] = {rA.x, rA.y, rA.z, rA.w, rB.x, rB.y, rB.z, rB.w};

        // Batch the (cheap, independent) LDS lookups for live edges first.
        int pp[8];
        bool live[8];
        #pragma unroll
        for (int k = 0; k < 8; k++) {
            live[k] = rv[k] < 6.0f;
            unsigned wi = live[k] ? tbl[ii[k] >> 4] : 0u;
            unsigned wj = live[k] ? tbl[jj[k] >> 4] : 0u;
            int ti = (wi >> ((ii[k] & 15) << 1)) & 3;
            int tj = (wj >> ((jj[k] & 15) << 1)) & 3;
            pp[k] = (ti << 2) | tj;
        }

        #pragma unroll
        for (int k = 0; k < 8; k++) {
            if (!live[k]) continue;
            const int   p  = pp[k];
            const float rk = rv[k];

            const float e1 = ex2_approx(s_a1[p] * rk);
            const float e2 = ex2_approx(s_a2[p] * rk);
            const float e3 = ex2_approx(s_a3[p] * rk);
            const float e4 = ex2_approx(s_a4[p] * rk);
            float psi = fmaf(0.02817f, e1,
                        fmaf(0.28022f, e2,
                        fmaf(0.50986f, e3, 0.18175f * e4)));

            // Polynomial cutoff, p=6: 1 - 28 rr^6 + 48 rr^7 - 21 rr^8
            const float rr  = rk * ZBL_INV_RMAX;
            const float rr2 = rr * rr;
            const float rr3 = rr2 * rr;
            const float rr6 = rr3 * rr3;
            const float cut = fmaf(rr6, fmaf(rr, fmaf(rr, -21.0f, 48.0f), -28.0f), 1.0f);

            const float eng = s_zzq[p] * psi * rcp_approx(rk);
            atomicAdd(&out[ii[k]], eng * cut);
        }
    }

    // Scalar tail (E not divisible by 8): at most 7 edges, one thread.
    if (blockIdx.x == 0 && tid == 0) {
        for (int e = nvec8 << 3; e < E; e++) {
            float rk = r[e];
            if (rk >= 6.0f) continue;
            int i = e_i[e], j = e_j[e];
            unsigned wi = tbl[i >> 4];
            unsigned wj = tbl[j >> 4];
            int ti = (wi >> ((i & 15) << 1)) & 3;
            int tj = (wj >> ((j & 15) << 1)) & 3;
            int p = (ti << 2) | tj;
            float e1 = ex2_approx(s_a1[p] * rk);
            float e2 = ex2_approx(s_a2[p] * rk);
            float e3 = ex2_approx(s_a3[p] * rk);
            float e4 = ex2_approx(s_a4[p] * rk);
            float psi = fmaf(0.02817f, e1,
                        fmaf(0.28022f, e2,
                        fmaf(0.50986f, e3, 0.18175f * e4)));
            float rr  = rk * ZBL_INV_RMAX;
            float rr2 = rr * rr;
            float rr6 = rr2 * rr2 * rr2;
            float cut = fmaf(rr6, fmaf(rr, fmaf(rr, -21.0f, 48.0f), -28.0f), 1.0f);
            float eng = s_zzq[p] * psi * rcp_approx(rk);
            atomicAdd(&out[i], eng * cut);
        }
    }
}

extern "C" void kernel_launch(void* const* d_in, const int* in_sizes, int n_in,
                              void* d_out, int out_size)
{
    const float* Z     = (const float*)d_in[0];
    const float* r     = (const float*)d_in[1];
    const float* pae   = (const float*)d_in[2];
    const int*   types = (const int*)d_in[3];
    const int*   eidx  = (const int*)d_in[4];
    float*       out   = (float*)d_out;

    const int E       = in_sizes[1];
    const int n_atoms = in_sizes[2];
    const int n_words = (n_atoms + 15) >> 4;

    {
        int work = (n_atoms >> 2) > n_words ? (n_atoms >> 2) : n_words;
        if (work < 1) work = 1;
        prep_kernel<<<(work + 255) / 256, 256>>>(pae, out, types, n_atoms, n_words);
    }

    // Persistent-style grid: 8 blocks/SM (26KB smem each) x ~152 SMs.
    const int blocks = 1216;
    if (n_words <= SMEM_WORDS) {
        zbl_edge_kernel<true><<<blocks, 256>>>(r, eidx, eidx + E, Z, out, E, n_words);
    } else {
        zbl_edge_kernel<false><<<blocks, 256>>>(r, eidx, eidx + E, Z, out, E, n_words);
    }
}

// round 8
// speedup vs baseline: 1.0936x; 1.0936x over previous
#include <cuda_runtime.h>

// ZBL pair energy + segment-sum into per-atom energies.
//
// Inputs (metadata order; JAX default x64-off stores "int64" as int32):
//   d_in[0] Z               float32 [4]
//   d_in[1] r               float32 [E]          (E = 6,400,000)
//   d_in[2] per_atom_energy float32 [n_atoms,1]  (n_atoms = 100,000)
//   d_in[3] atom_types      int32   [n_atoms]
//   d_in[4] edge_index      int32   [2, E]
// Output: float32 [n_atoms, 1]

#define ZBL_QQ        7.1998225f        // 14.399645 * 0.5
#define ZBL_INV_A0    (1.0f / 0.4685f)
#define ZBL_INV_RMAX  (1.0f / 6.0f)
#define LOG2E         1.4426950408889634f
// ZBL decay constants pre-multiplied by log2(e) is folded into `base`; the
// d_k stay as immediates on the FMA pipe.
#define ZBL_D1 (-0.20162f)
#define ZBL_D2 (-0.40290f)
#define ZBL_D3 (-0.94229f)
#define ZBL_D4 (-3.19980f)

// Shared-memory LUT capacity: 6400 words * 16 types = 102400 atoms.
#define SMEM_WORDS 6400
// Fallback global packed buffer: 1M words = 16M atoms (4MB static).
#define MAX_PACK_WORDS (1 << 20)
__device__ unsigned g_packed_types[MAX_PACK_WORDS];

__device__ __forceinline__ float ex2_approx(float x) {
    float y; asm("ex2.approx.f32 %0, %1;" : "=f"(y) : "f"(x)); return y;
}
__device__ __forceinline__ float rcp_approx(float x) {
    float y; asm("rcp.approx.f32 %0, %1;" : "=f"(y) : "f"(x)); return y;
}

// Fused prep: out = per_atom_energy (float4 copy) AND pack types 2-bit/atom.
__global__ void prep_kernel(const float* __restrict__ pae,
                            float* __restrict__ out,
                            const int* __restrict__ types,
                            int n_atoms, int n_words)
{
    const int i = blockIdx.x * blockDim.x + threadIdx.x;
    const int nvec4 = n_atoms >> 2;

    if (i < nvec4)
        reinterpret_cast<float4*>(out)[i] =
            reinterpret_cast<const float4*>(pae)[i];
    if (i == 0)
        for (int a = nvec4 << 2; a < n_atoms; a++) out[a] = pae[a];

    if (i < n_words) {
        unsigned v = 0;
        const int base = i << 4;
        if (base + 16 <= n_atoms) {
            const int4* t4 = reinterpret_cast<const int4*>(types + base);
            #pragma unroll
            for (int q = 0; q < 4; q++) {
                int4 w = t4[q];
                v |= ((unsigned)w.x & 3u) << ((q * 4 + 0) * 2);
                v |= ((unsigned)w.y & 3u) << ((q * 4 + 1) * 2);
                v |= ((unsigned)w.z & 3u) << ((q * 4 + 2) * 2);
                v |= ((unsigned)w.w & 3u) << ((q * 4 + 3) * 2);
            }
        } else {
            for (int k = 0; k < 16; k++) {
                int a = base + k;
                unsigned t = (a < n_atoms) ? ((unsigned)types[a] & 3u) : 0u;
                v |= t << (k * 2);
            }
        }
        g_packed_types[i] = v;
    }
}

// Per-edge ZBL energy, scattered with atomicAdd. 4 edges per thread-iteration.
template <bool USE_SMEM>
__global__ void __launch_bounds__(256, 8)
zbl_edge_kernel(const float* __restrict__ r,
                const int* __restrict__ e_i,   // edge_index row 0 (segment target)
                const int* __restrict__ e_j,   // edge_index row 1
                const float* __restrict__ Z,
                float* __restrict__ out,
                int E, int n_words)
{
    __shared__ unsigned s_pack[USE_SMEM ? SMEM_WORDS : 1];
    // Per-pair: x = (Zi^0.23 + Zj^0.23)/a0 * log2e,  y = QQ*Zi*Zj
    __shared__ float2 s_pair[16];
    __shared__ float s_zp[4], s_z[4];

    const int tid = threadIdx.x;
    if (tid < 4) {
        float z = Z[tid];
        s_z[tid]  = z;
        s_zp[tid] = __powf(z, 0.23f);
    }
    __syncthreads();
    if (tid < 16) {
        int ti = tid >> 2, tj = tid & 3;
        s_pair[tid] = make_float2(
            (s_zp[ti] + s_zp[tj]) * ZBL_INV_A0 * LOG2E,
            ZBL_QQ * s_z[ti] * s_z[tj]);
    }
    if (USE_SMEM) {
        for (int w = tid; w < n_words; w += 256)
            s_pack[w] = g_packed_types[w];
    }
    __syncthreads();

    const unsigned* __restrict__ tbl = USE_SMEM ? s_pack : g_packed_types;

    const int nvec   = E >> 2;          // 4 edges per iteration
    const int stride = gridDim.x * blockDim.x;

    for (int t = blockIdx.x * blockDim.x + tid; t < nvec; t += stride) {
        // Front-batched wide loads: 3 x 16B (MLP = 3).
        const float4 r4 = __ldg(reinterpret_cast<const float4*>(r) + t);
        const int4   i4 = __ldg(reinterpret_cast<const int4*>(e_i) + t);
        const int4   j4 = __ldg(reinterpret_cast<const int4*>(e_j) + t);

        int   ii[4] = {i4.x, i4.y, i4.z, i4.w};
        int   jj[4] = {j4.x, j4.y, j4.z, j4.w};
        float rv[4] = {r4.x, r4.y, r4.z, r4.w};

        #pragma unroll
        for (int k = 0; k < 4; k++) {
            const float rk = rv[k];
            if (rk >= 6.0f) continue;

            // 2-bit type lookup (2x LDS) + one LDS.64 pair-table read.
            const unsigned wi = tbl[ii[k] >> 4];
            const unsigned wj = tbl[jj[k] >> 4];
            const int ti = (wi >> ((ii[k] & 15) << 1)) & 3;
            const int tj = (wj >> ((jj[k] & 15) << 1)) & 3;
            const float2 pr = s_pair[(ti << 2) | tj];

            // psi: exp args = d_k * base * rk (ex2 with log2e folded into base).
            const float brk = pr.x * rk;
            const float e1 = ex2_approx(ZBL_D1 * brk);
            const float e2 = ex2_approx(ZBL_D2 * brk);
            const float e3 = ex2_approx(ZBL_D3 * brk);
            const float e4 = ex2_approx(ZBL_D4 * brk);
            float psi = fmaf(0.02817f, e1,
                        fmaf(0.28022f, e2,
                        fmaf(0.50986f, e3, 0.18175f * e4)));

            // Polynomial cutoff, p=6: 1 - 28 rr^6 + 48 rr^7 - 21 rr^8
            const float rr  = rk * ZBL_INV_RMAX;
            const float rr2 = rr * rr;
            const float rr3 = rr2 * rr;
            const float rr6 = rr3 * rr3;
            const float cut = fmaf(rr6, fmaf(rr, fmaf(rr, -21.0f, 48.0f), -28.0f), 1.0f);

            const float eng = pr.y * psi * rcp_approx(rk);
            atomicAdd(&out[ii[k]], eng * cut);
        }
    }

    // Scalar tail (E not divisible by 4): at most 3 edges, one thread.
    if (blockIdx.x == 0 && tid == 0) {
        for (int e = nvec << 2; e < E; e++) {
            float rk = r[e];
            if (rk >= 6.0f) continue;
            int i = e_i[e], j = e_j[e];
            unsigned wi = tbl[i >> 4];
            unsigned wj = tbl[j >> 4];
            int ti = (wi >> ((i & 15) << 1)) & 3;
            int tj = (wj >> ((j & 15) << 1)) & 3;
            float2 pr = s_pair[(ti << 2) | tj];
            float brk = pr.x * rk;
            float e1 = ex2_approx(ZBL_D1 * brk);
            float e2 = ex2_approx(ZBL_D2 * brk);
            float e3 = ex2_approx(ZBL_D3 * brk);
            float e4 = ex2_approx(ZBL_D4 * brk);
            float psi = fmaf(0.02817f, e1,
                        fmaf(0.28022f, e2,
                        fmaf(0.50986f, e3, 0.18175f * e4)));
            float rr  = rk * ZBL_INV_RMAX;
            float rr2 = rr * rr;
            float rr6 = rr2 * rr2 * rr2;
            float cut = fmaf(rr6, fmaf(rr, fmaf(rr, -21.0f, 48.0f), -28.0f), 1.0f);
            float eng = pr.y * psi * rcp_approx(rk);
            atomicAdd(&out[i], eng * cut);
        }
    }
}

extern "C" void kernel_launch(void* const* d_in, const int* in_sizes, int n_in,
                              void* d_out, int out_size)
{
    const float* Z     = (const float*)d_in[0];
    const float* r     = (const float*)d_in[1];
    const float* pae   = (const float*)d_in[2];
    const int*   types = (const int*)d_in[3];
    const int*   eidx  = (const int*)d_in[4];
    float*       out   = (float*)d_out;

    const int E       = in_sizes[1];
    const int n_atoms = in_sizes[2];
    const int n_words = (n_atoms + 15) >> 4;

    {
        int work = (n_atoms >> 2) > n_words ? (n_atoms >> 2) : n_words;
        if (work < 1) work = 1;
        prep_kernel<<<(work + 255) / 256, 256>>>(pae, out, types, n_atoms, n_words);
    }

    // Persistent grid: 8 blocks/SM (26KB smem each) x 152 SMs.
    const int blocks = 1216;
    if (n_words <= SMEM_WORDS) {
        zbl_edge_kernel<true><<<blocks, 256>>>(r, eidx, eidx + E, Z, out, E, n_words);
    } else {
        zbl_edge_kernel<false><<<blocks, 256>>>(r, eidx, eidx + E, Z, out, E, n_words);
    }
}

// round 9
// speedup vs baseline: 1.1472x; 1.0491x over previous
#include <cuda_runtime.h>

// ZBL pair energy + segment-sum into per-atom energies.
//
// Inputs (metadata order; JAX default x64-off stores "int64" as int32):
//   d_in[0] Z               float32 [4]
//   d_in[1] r               float32 [E]          (E = 6,400,000)
//   d_in[2] per_atom_energy float32 [n_atoms,1]  (n_atoms = 100,000)
//   d_in[3] atom_types      int32   [n_atoms]
//   d_in[4] edge_index      int32   [2, E]
// Output: float32 [n_atoms, 1]

#define ZBL_QQ        7.1998225f        // 14.399645 * 0.5
#define ZBL_INV_A0    (1.0f / 0.4685f)
#define ZBL_INV_RMAX  (1.0f / 6.0f)
#define LOG2E         1.4426950408889634f
#define ZBL_D1 (-0.20162f)
#define ZBL_D2 (-0.40290f)
#define ZBL_D3 (-0.94229f)
#define ZBL_D4 (-3.19980f)

// Shared-memory LUT capacity: 6400 words * 16 types = 102400 atoms.
#define SMEM_WORDS 6400
// Fallback global packed buffer: 1M words = 16M atoms (4MB static).
#define MAX_PACK_WORDS (1 << 20)
__device__ unsigned g_packed_types[MAX_PACK_WORDS];

__device__ __forceinline__ float ex2_approx(float x) {
    float y; asm("ex2.approx.f32 %0, %1;" : "=f"(y) : "f"(x)); return y;
}
__device__ __forceinline__ float rcp_approx(float x) {
    float y; asm("rcp.approx.f32 %0, %1;" : "=f"(y) : "f"(x)); return y;
}

// Fused prep: out = per_atom_energy (float4 copy) AND pack types 2-bit/atom.
__global__ void prep_kernel(const float* __restrict__ pae,
                            float* __restrict__ out,
                            const int* __restrict__ types,
                            int n_atoms, int n_words)
{
    const int i = blockIdx.x * blockDim.x + threadIdx.x;
    const int nvec4 = n_atoms >> 2;

    if (i < nvec4)
        reinterpret_cast<float4*>(out)[i] =
            reinterpret_cast<const float4*>(pae)[i];
    if (i == 0)
        for (int a = nvec4 << 2; a < n_atoms; a++) out[a] = pae[a];

    if (i < n_words) {
        unsigned v = 0;
        const int base = i << 4;
        if (base + 16 <= n_atoms) {
            const int4* t4 = reinterpret_cast<const int4*>(types + base);
            #pragma unroll
            for (int q = 0; q < 4; q++) {
                int4 w = t4[q];
                v |= ((unsigned)w.x & 3u) << ((q * 4 + 0) * 2);
                v |= ((unsigned)w.y & 3u) << ((q * 4 + 1) * 2);
                v |= ((unsigned)w.z & 3u) << ((q * 4 + 2) * 2);
                v |= ((unsigned)w.w & 3u) << ((q * 4 + 3) * 2);
            }
        } else {
            for (int k = 0; k < 16; k++) {
                int a = base + k;
                unsigned t = (a < n_atoms) ? ((unsigned)types[a] & 3u) : 0u;
                v |= t << (k * 2);
            }
        }
        g_packed_types[i] = v;
    }
}

// Body for 4 edges (branchless except the predicated atomic).
template <bool USE_SMEM>
__device__ __forceinline__ void process4(const unsigned* __restrict__ tbl,
                                         const float2* __restrict__ s_pair,
                                         float* __restrict__ out,
                                         float4 r4, int4 i4, int4 j4)
{
    int   ii[4] = {i4.x, i4.y, i4.z, i4.w};
    int   jj[4] = {j4.x, j4.y, j4.z, j4.w};
    float rv[4] = {r4.x, r4.y, r4.z, r4.w};

    bool   live[4];
    float2 pr[4];
    #pragma unroll
    for (int k = 0; k < 4; k++) {
        live[k] = rv[k] < 6.0f;
        const int ia = live[k] ? ii[k] : 0;    // clamp dead lanes
        const int ja = live[k] ? jj[k] : 0;
        const unsigned wi = tbl[ia >> 4];
        const unsigned wj = tbl[ja >> 4];
        const int ti = (wi >> ((ia & 15) << 1)) & 3;
        const int tj = (wj >> ((ja & 15) << 1)) & 3;
        pr[k] = s_pair[(ti << 2) | tj];
    }

    #pragma unroll
    for (int k = 0; k < 4; k++) {
        const float rk = rv[k];

        const float brk = pr[k].x * rk;
        const float e1 = ex2_approx(ZBL_D1 * brk);
        const float e2 = ex2_approx(ZBL_D2 * brk);
        const float e3 = ex2_approx(ZBL_D3 * brk);
        const float e4 = ex2_approx(ZBL_D4 * brk);
        float psi = fmaf(0.02817f, e1,
                    fmaf(0.28022f, e2,
                    fmaf(0.50986f, e3, 0.18175f * e4)));

        // Polynomial cutoff, p=6: 1 - 28 rr^6 + 48 rr^7 - 21 rr^8
        const float rr  = rk * ZBL_INV_RMAX;
        const float rr2 = rr * rr;
        const float rr3 = rr2 * rr;
        const float rr6 = rr3 * rr3;
        const float cut = fmaf(rr6, fmaf(rr, fmaf(rr, -21.0f, 48.0f), -28.0f), 1.0f);

        const float eng = pr[k].y * psi * rcp_approx(rk) * cut;
        if (live[k]) atomicAdd(&out[ii[k]], eng);
    }
}

// Per-edge ZBL energy, scattered with atomicAdd. 4 edges per thread-iteration,
// software-pipelined (depth 2) across grid-stride iterations.
template <bool USE_SMEM>
__global__ void __launch_bounds__(256)
zbl_edge_kernel(const float* __restrict__ r,
                const int* __restrict__ e_i,
                const int* __restrict__ e_j,
                const float* __restrict__ Z,
                float* __restrict__ out,
                int E, int n_words)
{
    __shared__ unsigned s_pack[USE_SMEM ? SMEM_WORDS : 1];
    // Per-pair: x = (Zi^0.23 + Zj^0.23)/a0 * log2e,  y = QQ*Zi*Zj
    __shared__ float2 s_pair[16];
    __shared__ float s_zp[4], s_z[4];

    const int tid = threadIdx.x;
    if (tid < 4) {
        float z = Z[tid];
        s_z[tid]  = z;
        s_zp[tid] = __powf(z, 0.23f);
    }
    __syncthreads();
    if (tid < 16) {
        int ti = tid >> 2, tj = tid & 3;
        s_pair[tid] = make_float2(
            (s_zp[ti] + s_zp[tj]) * ZBL_INV_A0 * LOG2E,
            ZBL_QQ * s_z[ti] * s_z[tj]);
    }
    if (USE_SMEM) {
        for (int w = tid; w < n_words; w += 256)
            s_pack[w] = g_packed_types[w];
    }
    __syncthreads();

    const unsigned* __restrict__ tbl = USE_SMEM ? s_pack : g_packed_types;

    const int nvec   = E >> 2;
    const int stride = gridDim.x * blockDim.x;
    int t = blockIdx.x * blockDim.x + tid;

    if (t < nvec) {
        // Prologue: load first tile.
        float4 r4 = __ldcs(reinterpret_cast<const float4*>(r) + t);
        int4   i4 = __ldcs(reinterpret_cast<const int4*>(e_i) + t);
        int4   j4 = __ldcs(reinterpret_cast<const int4*>(e_j) + t);

        for (;;) {
            const int tn = t + stride;
            const bool more = tn < nvec;

            // Prefetch next tile before computing current (latency overlap).
            float4 r4n; int4 i4n, j4n;
            if (more) {
                r4n = __ldcs(reinterpret_cast<const float4*>(r) + tn);
                i4n = __ldcs(reinterpret_cast<const int4*>(e_i) + tn);
                j4n = __ldcs(reinterpret_cast<const int4*>(e_j) + tn);
            }

            process4<USE_SMEM>(tbl, s_pair, out, r4, i4, j4);

            if (!more) break;
            r4 = r4n; i4 = i4n; j4 = j4n; t = tn;
        }
    }

    // Scalar tail (E not divisible by 4): at most 3 edges, one thread.
    if (blockIdx.x == 0 && tid == 0) {
        for (int e = nvec << 2; e < E; e++) {
            float rk = r[e];
            if (rk >= 6.0f) continue;
            int i = e_i[e], j = e_j[e];
            unsigned wi = tbl[i >> 4];
            unsigned wj = tbl[j >> 4];
            int ti = (wi >> ((i & 15) << 1)) & 3;
            int tj = (wj >> ((j & 15) << 1)) & 3;
            float2 pr = s_pair[(ti << 2) | tj];
            float brk = pr.x * rk;
            float e1 = ex2_approx(ZBL_D1 * brk);
            float e2 = ex2_approx(ZBL_D2 * brk);
            float e3 = ex2_approx(ZBL_D3 * brk);
            float e4 = ex2_approx(ZBL_D4 * brk);
            float psi = fmaf(0.02817f, e1,
                        fmaf(0.28022f, e2,
                        fmaf(0.50986f, e3, 0.18175f * e4)));
            float rr  = rk * ZBL_INV_RMAX;
            float rr2 = rr * rr;
            float rr6 = rr2 * rr2 * rr2;
            float cut = fmaf(rr6, fmaf(rr, fmaf(rr, -21.0f, 48.0f), -28.0f), 1.0f);
            float eng = pr.y * psi * rcp_approx(rk);
            atomicAdd(&out[i], eng * cut);
        }
    }
}

extern "C" void kernel_launch(void* const* d_in, const int* in_sizes, int n_in,
                              void* d_out, int out_size)
{
    const float* Z     = (const float*)d_in[0];
    const float* r     = (const float*)d_in[1];
    const float* pae   = (const float*)d_in[2];
    const int*   types = (const int*)d_in[3];
    const int*   eidx  = (const int*)d_in[4];
    float*       out   = (float*)d_out;

    const int E       = in_sizes[1];
    const int n_atoms = in_sizes[2];
    const int n_words = (n_atoms + 15) >> 4;

    {
        int work = (n_atoms >> 2) > n_words ? (n_atoms >> 2) : n_words;
        if (work < 1) work = 1;
        prep_kernel<<<(work + 255) / 256, 256>>>(pae, out, types, n_atoms, n_words);
    }

    const int blocks = 1216;
    if (n_words <= SMEM_WORDS) {
        zbl_edge_kernel<true><<<blocks, 256>>>(r, eidx, eidx + E, Z, out, E, n_words);
    } else {
        zbl_edge_kernel<false><<<blocks, 256>>>(r, eidx, eidx + E, Z, out, E, n_words);
    }
}